// round 5
// baseline (speedup 1.0000x reference)
#include <cuda_runtime.h>
#include <cstdint>

#define NB    64
#define PW    68          // 64 + 2*2 x-halo
#define ROWS  32          // rows owned per CTA (half image)
#define VROWS 36          // 32 + 2*2 y-halo
#define VBUF  (VROWS*PW)  // 2448
#define MROWS 40          // maze rows needed: base-4 .. base+35
#define NPIX  4096
#define NTH   512

__device__ float g_T[104];   // T[tap][z], z in 0..3 (3 = zero-pad sentinel)
__device__ float g_effb;

// ---------------------------------------------------------------------------
// Prep: collapse encode_w(150x2x5x5)+r_w(150)+emb(3x2) -> 25-tap x 4-symbol LUT
// ---------------------------------------------------------------------------
__global__ void prep_kernel(const float* __restrict__ emb,
                            const float* __restrict__ encode_w,
                            const float* __restrict__ encode_b,
                            const float* __restrict__ r_w) {
    __shared__ float effw[50];
    int t = threadIdx.x;
    if (t < 50) {
        float s = 0.f;
        for (int c = 0; c < 150; ++c) s = fmaf(r_w[c], encode_w[c * 50 + t], s);
        effw[t] = s;
    }
    __syncthreads();
    if (t < 25) {
        float w0 = effw[t], w1 = effw[25 + t];
        #pragma unroll
        for (int z = 0; z < 3; ++z)
            g_T[t * 4 + z] = w0 * emb[2 * z] + w1 * emb[2 * z + 1];
        g_T[t * 4 + 3] = 0.f;
    } else if (t == 32) {
        float s = 0.f;
        for (int c = 0; c < 150; ++c) s = fmaf(r_w[c], encode_b[c], s);
        g_effb = s;
    }
}

// -------- cluster helpers ---------------------------------------------------
__device__ __forceinline__ void st_remote_f32(float* p, uint32_t peer, float v) {
    uint32_t a = (uint32_t)__cvta_generic_to_shared(p);
    uint32_t ra;
    asm("mapa.shared::cluster.u32 %0, %1, %2;" : "=r"(ra) : "r"(a), "r"(peer));
    asm volatile("st.shared::cluster.f32 [%0], %1;" :: "r"(ra), "f"(v) : "memory");
}
__device__ __forceinline__ void cluster_sync_all() {
    asm volatile("barrier.cluster.arrive.aligned;" ::: "memory");
    asm volatile("barrier.cluster.wait.aligned;" ::: "memory");
}

// ---------------------------------------------------------------------------
// VIN kernel: 2-CTA cluster per image. Each CTA owns 32 rows; 2-row v-halos
// are pushed to the peer via DSMEM each iteration. 512 threads: x = tid&63,
// strip s = tid>>6 owns own-rows 4s..4s+3 (all LDS lane-stride-1).
// ---------------------------------------------------------------------------
__global__ __launch_bounds__(NTH, 1) __cluster_dims__(2, 1, 1)
void vin_kernel(const int* __restrict__ maze,
                const float* __restrict__ q_w,
                const float* __restrict__ w_in,
                const float* __restrict__ fc_w,
                float* __restrict__ out) {
    extern __shared__ float sm[];
    float* bufA = sm;                    // v ping  (rows base-2..base+33)
    float* bufB = sm + VBUF;             // v pong
    float* r_s  = sm + 2 * VBUF;         // r, same row range, zero-padded
    float* Rq_s = sm + 3 * VBUF;         // [8][32][64] iteration-invariant
    float* T_s  = Rq_s + 8 * ROWS * 64;  // 104
    float* qw_s = T_s + 104;             // 200
    float* w_s  = qw_s + 200;            // 200
    float* fc_s = w_s + 200;             // 32

    const int tid  = threadIdx.x;
    const int b    = blockIdx.x >> 1;
    const uint32_t rank = blockIdx.x & 1;
    const uint32_t peer = rank ^ 1u;
    const int base = (int)rank * ROWS;   // first global row owned
    const int x    = tid & 63;
    const int s    = tid >> 6;           // 0..7
    const int r0   = s << 2;             // first own local row (0..28)

    int* m_tile = (int*)Rq_s;            // alias: maze tile only needed pre-Rq

    // --- init
    for (int i = tid; i < VBUF; i += NTH) { bufA[i] = 0.f; bufB[i] = 0.f; r_s[i] = 0.f; }
    for (int i = tid; i < MROWS * PW; i += NTH) m_tile[i] = 3;
    for (int i = tid; i < 200; i += NTH) { qw_s[i] = q_w[i]; w_s[i] = w_in[i]; }
    if (tid < 104) T_s[tid] = g_T[tid];
    if (tid < 32)  fc_s[tid] = fc_w[tid];
    __syncthreads();

    const int* mz = maze + b * NPIX;
    for (int i = tid; i < MROWS * 64; i += NTH) {
        int lr = i >> 6;                 // 0..39 -> global row base-4+lr
        int gr = base - 4 + lr;
        int gc = i & 63;
        if (gr >= 0 && gr < 64)
            m_tile[lr * PW + gc + 2] = mz[gr * 64 + gc];
    }
    __syncthreads();

    // --- phase 1: r on extended rows base-2..base+33 (in-image only)
    {
        const float effb = g_effb;
        for (int p = tid; p < VROWS * 64; p += NTH) {
            int lr = p >> 6;             // 0..35 -> global row base-2+lr
            int gr = base - 2 + lr;
            int gc = p & 63;
            if (gr < 0 || gr >= 64) continue;
            float acc = effb;
            #pragma unroll
            for (int ky = 0; ky < 5; ++ky)
                #pragma unroll
                for (int kx = 0; kx < 5; ++kx)
                    acc += T_s[(ky * 5 + kx) * 4 + m_tile[(lr + ky) * PW + gc + kx]];
            r_s[lr * PW + gc + 2] = acc;
        }
    }
    __syncthreads();   // m_tile dead; Rq_s may now be written

    // --- phase 2: Rq = conv(r, q_w) for own rows; v1 = max_a Rq; push halos
    {
        float rwin[8][5];
        #pragma unroll
        for (int dy = 0; dy < 8; ++dy)
            #pragma unroll
            for (int dx = 0; dx < 5; ++dx)
                rwin[dy][dx] = r_s[(r0 + dy) * PW + x + dx];
        float vmax[4];
        #pragma unroll
        for (int a = 0; a < 8; ++a) {
            float acc[4] = {0.f, 0.f, 0.f, 0.f};
            #pragma unroll
            for (int ky = 0; ky < 5; ++ky)
                #pragma unroll
                for (int kx = 0; kx < 5; ++kx) {
                    float c = qw_s[a * 25 + ky * 5 + kx];
                    #pragma unroll
                    for (int j = 0; j < 4; ++j)
                        acc[j] = fmaf(c, rwin[j + ky][kx], acc[j]);
                }
            #pragma unroll
            for (int j = 0; j < 4; ++j) {
                Rq_s[a * (ROWS * 64) + (r0 + j) * 64 + x] = acc[j];
                vmax[j] = (a == 0) ? acc[j] : fmaxf(vmax[j], acc[j]);
            }
        }
        #pragma unroll
        for (int j = 0; j < 4; ++j)
            bufA[(r0 + j + 2) * PW + x + 2] = vmax[j];
        if (rank == 0) {            // own rows 30,31 -> peer buffer rows 0,1
            if (s == 7) {
                st_remote_f32(&bufA[0 * PW + x + 2], peer, vmax[2]);
                st_remote_f32(&bufA[1 * PW + x + 2], peer, vmax[3]);
            }
        } else {                    // own rows 0,1 -> peer buffer rows 34,35
            if (s == 0) {
                st_remote_f32(&bufA[34 * PW + x + 2], peer, vmax[0]);
                st_remote_f32(&bufA[35 * PW + x + 2], peer, vmax[1]);
            }
        }
    }
    __syncthreads();
    cluster_sync_all();

    // --- 9 value-iteration steps; Rq resident, halos exchanged per step
    float* vin  = bufA;
    float* vout = bufB;
    for (int t = 0; t < 9; ++t) {
        float vw[8][5];
        #pragma unroll
        for (int dy = 0; dy < 8; ++dy)
            #pragma unroll
            for (int dx = 0; dx < 5; ++dx)
                vw[dy][dx] = vin[(r0 + dy) * PW + x + dx];
        float vmax[4];
        #pragma unroll
        for (int a = 0; a < 8; ++a) {
            float acc[4] = {0.f, 0.f, 0.f, 0.f};
            #pragma unroll
            for (int ky = 0; ky < 5; ++ky)
                #pragma unroll
                for (int kx = 0; kx < 5; ++kx) {
                    float c = w_s[a * 25 + ky * 5 + kx];
                    #pragma unroll
                    for (int j = 0; j < 4; ++j)
                        acc[j] = fmaf(c, vw[j + ky][kx], acc[j]);
                }
            #pragma unroll
            for (int j = 0; j < 4; ++j) {
                float qa = acc[j] + Rq_s[a * (ROWS * 64) + (r0 + j) * 64 + x];
                vmax[j] = (a == 0) ? qa : fmaxf(vmax[j], qa);
            }
        }
        #pragma unroll
        for (int j = 0; j < 4; ++j)
            vout[(r0 + j + 2) * PW + x + 2] = vmax[j];
        if (rank == 0) {
            if (s == 7) {
                st_remote_f32(&vout[0 * PW + x + 2], peer, vmax[2]);
                st_remote_f32(&vout[1 * PW + x + 2], peer, vmax[3]);
            }
        } else {
            if (s == 0) {
                st_remote_f32(&vout[34 * PW + x + 2], peer, vmax[0]);
                st_remote_f32(&vout[35 * PW + x + 2], peer, vmax[1]);
            }
        }
        __syncthreads();
        cluster_sync_all();
        float* tmp = vin; vin = vout; vout = tmp;
    }

    // --- final step folded into fc matvec: out = fc( Rq + conv(v10, w) )
    {
        float vw[8][5];
        #pragma unroll
        for (int dy = 0; dy < 8; ++dy)
            #pragma unroll
            for (int dx = 0; dx < 5; ++dx)
                vw[dy][dx] = vin[(r0 + dy) * PW + x + dx];
        float o0[4], o1[4], o2[4], o3[4];
        #pragma unroll
        for (int j = 0; j < 4; ++j) { o0[j]=0.f; o1[j]=0.f; o2[j]=0.f; o3[j]=0.f; }
        #pragma unroll
        for (int a = 0; a < 8; ++a) {
            float acc[4] = {0.f, 0.f, 0.f, 0.f};
            #pragma unroll
            for (int ky = 0; ky < 5; ++ky)
                #pragma unroll
                for (int kx = 0; kx < 5; ++kx) {
                    float c = w_s[a * 25 + ky * 5 + kx];
                    #pragma unroll
                    for (int j = 0; j < 4; ++j)
                        acc[j] = fmaf(c, vw[j + ky][kx], acc[j]);
                }
            float f0 = fc_s[a], f1 = fc_s[8 + a], f2 = fc_s[16 + a], f3 = fc_s[24 + a];
            #pragma unroll
            for (int j = 0; j < 4; ++j) {
                float qa = acc[j] + Rq_s[a * (ROWS * 64) + (r0 + j) * 64 + x];
                o0[j] = fmaf(f0, qa, o0[j]);
                o1[j] = fmaf(f1, qa, o1[j]);
                o2[j] = fmaf(f2, qa, o2[j]);
                o3[j] = fmaf(f3, qa, o3[j]);
            }
        }
        float4* op = (float4*)(out + (size_t)b * NPIX * 4);
        #pragma unroll
        for (int j = 0; j < 4; ++j)
            op[(base + r0 + j) * 64 + x] = make_float4(o0[j], o1[j], o2[j], o3[j]);
    }
}

// ---------------------------------------------------------------------------
extern "C" void kernel_launch(void* const* d_in, const int* in_sizes, int n_in,
                              void* d_out, int out_size) {
    const int*   maze     = (const int*)d_in[0];
    const float* emb      = (const float*)d_in[1];
    const float* encode_w = (const float*)d_in[2];
    const float* encode_b = (const float*)d_in[3];
    const float* r_w      = (const float*)d_in[4];
    const float* q_w      = (const float*)d_in[5];
    const float* w_in     = (const float*)d_in[6];
    const float* fc_w     = (const float*)d_in[7];
    float* out = (float*)d_out;

    prep_kernel<<<1, 64>>>(emb, encode_w, encode_b, r_w);

    const int smem_bytes = (3 * VBUF + 8 * ROWS * 64 + 104 + 200 + 200 + 32)
                           * (int)sizeof(float);
    cudaFuncSetAttribute(vin_kernel,
                         cudaFuncAttributeMaxDynamicSharedMemorySize, smem_bytes);
    vin_kernel<<<NB * 2, NTH, smem_bytes>>>(maze, q_w, w_in, fc_w, out);
}